// round 1
// baseline (speedup 1.0000x reference)
#include <cuda_runtime.h>
#include <cuda_bf16.h>
#include <math.h>

// Problem constants
#define B   4
#define C   512
#define NPIX 4096            // 64*64
#define GROUPS 32
#define CPG (C/GROUPS)       // 16

// Scratch (allocation-free rule: __device__ globals)
__device__ float g_h[(long long)B*C*NPIX];          // normalized input  (b,c,p)
__device__ float g_qkv[(long long)B*3*C*NPIX];      // qkv               (b,o,p)
__device__ float g_attn[(long long)B*NPIX*NPIX];    // attention scores  (b,i,j)
__device__ float g_ao[(long long)B*NPIX*C];         // attn @ v          (b,i,c)

// ---------------------------------------------------------------------------
// GroupNorm: one block per (b, group). Group data is a contiguous chunk of
// CPG*NPIX = 65536 floats.
// ---------------------------------------------------------------------------
__global__ void groupnorm_kernel(const float* __restrict__ x,
                                 const float* __restrict__ gw,
                                 const float* __restrict__ gb,
                                 float* __restrict__ out)
{
    const int grp = blockIdx.x;                   // b*GROUPS + g
    const int g   = grp & (GROUPS - 1);
    const float4* xp = (const float4*)(x + (long long)grp * (CPG * NPIX));
    float4*       op = (float4*)(out + (long long)grp * (CPG * NPIX));
    const int tid = threadIdx.x;

    float s = 0.f, ss = 0.f;
    #pragma unroll 4
    for (int i = tid; i < (CPG * NPIX) / 4; i += 256) {
        float4 v = xp[i];
        s  += v.x + v.y + v.z + v.w;
        ss += v.x*v.x + v.y*v.y + v.z*v.z + v.w*v.w;
    }
    __shared__ float sh[64];
    #pragma unroll
    for (int o = 16; o; o >>= 1) {
        s  += __shfl_xor_sync(~0u, s, o);
        ss += __shfl_xor_sync(~0u, ss, o);
    }
    if ((tid & 31) == 0) { sh[tid >> 5] = s; sh[(tid >> 5) + 32] = ss; }
    __syncthreads();
    __shared__ float s_mu, s_rs;
    if (tid < 32) {
        float a = (tid < 8) ? sh[tid]      : 0.f;
        float b = (tid < 8) ? sh[tid + 32] : 0.f;
        #pragma unroll
        for (int o = 4; o; o >>= 1) {
            a += __shfl_xor_sync(~0u, a, o);
            b += __shfl_xor_sync(~0u, b, o);
        }
        if (tid == 0) {
            float mu  = a / (float)(CPG * NPIX);
            float var = b / (float)(CPG * NPIX) - mu * mu;
            s_mu = mu;
            s_rs = rsqrtf(var + 1e-5f);
        }
    }
    __syncthreads();
    const float mu = s_mu, rs = s_rs;

    #pragma unroll 4
    for (int i = tid; i < (CPG * NPIX) / 4; i += 256) {
        int c = (g << 4) + (i >> 10);             // 1024 float4 per channel
        float sc = gw[c] * rs;
        float sb = gb[c] - mu * sc;
        float4 v = xp[i];
        v.x = v.x * sc + sb;
        v.y = v.y * sc + sb;
        v.z = v.z * sc + sb;
        v.w = v.w * sc + sb;
        op[i] = v;
    }
}

// ---------------------------------------------------------------------------
// Generic strided batched SGEMM:
//   C[m,n] = alpha * sum_k A[m*sam + k*sak] * B[k*sbk + n*sbn]
//            (+ bias[m]) (+ resid[same layout as C])
// 64x64x16 tile, 256 threads, 4x4 register tile.
// All dims must be multiples of the tile (true for all 4 uses here).
// ---------------------------------------------------------------------------
#define BM 64
#define BN 64
#define BK 16

__global__ void __launch_bounds__(256)
sgemm_kernel(const float* __restrict__ A, const float* __restrict__ Bp,
             float* __restrict__ Cp,
             int M, int N, int K,
             long long sam, long long sak,
             long long sbk, long long sbn,
             long long scm, long long scn,
             long long bA, long long bB, long long bC,
             float alpha,
             const float* __restrict__ bias,
             const float* __restrict__ resid, long long bR)
{
    const int bz = blockIdx.z;
    A  += (long long)bz * bA;
    Bp += (long long)bz * bB;
    Cp += (long long)bz * bC;
    if (resid) resid += (long long)bz * bR;

    const int m0 = blockIdx.y * BM;
    const int n0 = blockIdx.x * BN;
    const int tid = threadIdx.x;
    const int tx = tid & 15, ty = tid >> 4;

    __shared__ float As[BK][BM];
    __shared__ float Bs[BK][BN];

    float acc[4][4] = {};

    for (int k0 = 0; k0 < K; k0 += BK) {
        #pragma unroll
        for (int i = 0; i < 4; i++) {
            int idx = tid + i * 256;
            int m, kk;
            if (sak == 1) { kk = idx & 15; m = idx >> 4; }   // A k-contiguous
            else          { m = idx & 63; kk = idx >> 6; }   // A m-contiguous
            As[kk][m] = A[(long long)(m0 + m) * sam + (long long)(k0 + kk) * sak];
            int n, kb;
            if (sbn == 1) { n = idx & 63; kb = idx >> 6; }   // B n-contiguous
            else          { kb = idx & 15; n = idx >> 4; }   // B k-contiguous
            Bs[kb][n] = Bp[(long long)(k0 + kb) * sbk + (long long)(n0 + n) * sbn];
        }
        __syncthreads();
        #pragma unroll
        for (int kk = 0; kk < BK; kk++) {
            float4 a4 = *(const float4*)&As[kk][ty * 4];
            float4 b4 = *(const float4*)&Bs[kk][tx * 4];
            float av[4] = {a4.x, a4.y, a4.z, a4.w};
            float bv[4] = {b4.x, b4.y, b4.z, b4.w};
            #pragma unroll
            for (int i = 0; i < 4; i++)
                #pragma unroll
                for (int j = 0; j < 4; j++)
                    acc[i][j] += av[i] * bv[j];
        }
        __syncthreads();
    }

    #pragma unroll
    for (int i = 0; i < 4; i++) {
        int m = m0 + ty * 4 + i;
        float bb = bias ? bias[m] : 0.f;
        #pragma unroll
        for (int j = 0; j < 4; j++) {
            int n = n0 + tx * 4 + j;
            float v = acc[i][j] * alpha + bb;
            long long ci = (long long)m * scm + (long long)n * scn;
            if (resid) v += resid[ci];
            Cp[ci] = v;
        }
    }
}

// ---------------------------------------------------------------------------
// Row softmax: one block per row of length 4096.
// ---------------------------------------------------------------------------
__global__ void softmax_kernel(float* __restrict__ S)
{
    float4* p = (float4*)(S + (long long)blockIdx.x * NPIX);
    const int tid = threadIdx.x;

    float4 v[4];
    float mx = -1e30f;
    #pragma unroll
    for (int i = 0; i < 4; i++) {
        v[i] = p[tid + i * 256];
        mx = fmaxf(mx, fmaxf(fmaxf(v[i].x, v[i].y), fmaxf(v[i].z, v[i].w)));
    }
    __shared__ float sh[32];
    #pragma unroll
    for (int o = 16; o; o >>= 1) mx = fmaxf(mx, __shfl_xor_sync(~0u, mx, o));
    if ((tid & 31) == 0) sh[tid >> 5] = mx;
    __syncthreads();
    if (tid < 32) {
        float m2 = (tid < 8) ? sh[tid] : -1e30f;
        #pragma unroll
        for (int o = 4; o; o >>= 1) m2 = fmaxf(m2, __shfl_xor_sync(~0u, m2, o));
        if (tid == 0) sh[0] = m2;
    }
    __syncthreads();
    mx = sh[0];
    __syncthreads();

    float s = 0.f;
    #pragma unroll
    for (int i = 0; i < 4; i++) {
        v[i].x = __expf(v[i].x - mx);
        v[i].y = __expf(v[i].y - mx);
        v[i].z = __expf(v[i].z - mx);
        v[i].w = __expf(v[i].w - mx);
        s += v[i].x + v[i].y + v[i].z + v[i].w;
    }
    #pragma unroll
    for (int o = 16; o; o >>= 1) s += __shfl_xor_sync(~0u, s, o);
    if ((tid & 31) == 0) sh[tid >> 5] = s;
    __syncthreads();
    if (tid < 32) {
        float s2 = (tid < 8) ? sh[tid] : 0.f;
        #pragma unroll
        for (int o = 4; o; o >>= 1) s2 += __shfl_xor_sync(~0u, s2, o);
        if (tid == 0) sh[0] = s2;
    }
    __syncthreads();
    const float inv = 1.f / sh[0];
    #pragma unroll
    for (int i = 0; i < 4; i++) {
        v[i].x *= inv; v[i].y *= inv; v[i].z *= inv; v[i].w *= inv;
        p[tid + i * 256] = v[i];
    }
}

// ---------------------------------------------------------------------------
extern "C" void kernel_launch(void* const* d_in, const int* in_sizes, int n_in,
                              void* d_out, int out_size)
{
    const float* x     = (const float*)d_in[0];
    const float* gn_w  = (const float*)d_in[1];
    const float* gn_b  = (const float*)d_in[2];
    const float* qkv_w = (const float*)d_in[3];
    const float* qkv_b = (const float*)d_in[4];
    const float* out_w = (const float*)d_in[5];
    const float* out_b = (const float*)d_in[6];
    float* out = (float*)d_out;

    void *ph, *pq, *pa, *po;
    cudaGetSymbolAddress(&ph, g_h);
    cudaGetSymbolAddress(&pq, g_qkv);
    cudaGetSymbolAddress(&pa, g_attn);
    cudaGetSymbolAddress(&po, g_ao);
    float* h    = (float*)ph;
    float* qkv  = (float*)pq;
    float* attn = (float*)pa;
    float* ao   = (float*)po;

    // 1) GroupNorm
    groupnorm_kernel<<<B * GROUPS, 256>>>(x, gn_w, gn_b, h);

    // 2) QKV: qkv[b,o,p] = sum_c W[o,c] * h[b,c,p] + bias[o]
    {
        dim3 grid(NPIX / BN, (3 * C) / BM, B);
        sgemm_kernel<<<grid, 256>>>(qkv_w, h, qkv,
            3 * C, NPIX, C,
            (long long)C, 1LL,              // A strides (o,c) row-major
            (long long)NPIX, 1LL,           // B strides (c,p)
            (long long)NPIX, 1LL,           // C strides (o,p)
            0LL, (long long)C * NPIX, (long long)3 * C * NPIX,
            1.0f, qkv_b, nullptr, 0LL);
    }

    // 3) Scores: S[b,i,j] = scale * sum_c q[b,c,i] * k[b,c,j]
    {
        dim3 grid(NPIX / BN, NPIX / BM, B);
        const float scale = 1.0f / sqrtf((float)C);
        sgemm_kernel<<<grid, 256>>>(qkv, qkv + (long long)C * NPIX, attn,
            NPIX, NPIX, C,
            1LL, (long long)NPIX,           // A = q: (i stride 1, c stride NPIX)
            (long long)NPIX, 1LL,           // B = k: (c stride NPIX, j stride 1)
            (long long)NPIX, 1LL,
            (long long)3 * C * NPIX, (long long)3 * C * NPIX,
            (long long)NPIX * NPIX,
            scale, nullptr, nullptr, 0LL);
    }

    // 4) Softmax over rows
    softmax_kernel<<<B * NPIX, 256>>>(attn);

    // 5) ao[b,i,c] = sum_j S[b,i,j] * v[b,c,j]
    {
        dim3 grid(C / BN, NPIX / BM, B);
        sgemm_kernel<<<grid, 256>>>(attn, qkv + (long long)2 * C * NPIX, ao,
            NPIX, C, NPIX,
            (long long)NPIX, 1LL,           // A = S row-major
            1LL, (long long)NPIX,           // B = v: (j stride 1, c stride NPIX)
            (long long)C, 1LL,              // C = ao (i,c)
            (long long)NPIX * NPIX, (long long)3 * C * NPIX,
            (long long)NPIX * C,
            1.0f, nullptr, nullptr, 0LL);
    }

    // 6) y[b,o,p] = sum_c out_w[o,c] * ao[b,p,c] + out_b[o] + x[b,o,p]
    {
        dim3 grid(NPIX / BN, C / BM, B);
        sgemm_kernel<<<grid, 256>>>(out_w, ao, out,
            C, NPIX, C,
            (long long)C, 1LL,              // A = out_w row-major
            1LL, (long long)C,              // B = ao: (c stride 1, p stride C)
            (long long)NPIX, 1LL,           // C = out (o,p)
            0LL, (long long)NPIX * C, (long long)C * NPIX,
            1.0f, out_b, x, (long long)C * NPIX);
    }
}

// round 2
// speedup vs baseline: 11.1778x; 11.1778x over previous
#include <cuda_runtime.h>
#include <cuda_bf16.h>
#include <math.h>
#include <stdint.h>

#define B_    4
#define C_    512
#define NPIX  4096
#define GROUPS 32
#define CPG   16

typedef __nv_bfloat16 bf16;

// ------------------- scratch (__device__ globals; allocation-free) ---------
__device__ bf16 g_hb[(size_t)B_ * NPIX * C_];        // h transposed (b,p,c)
__device__ bf16 g_w [(size_t)(3 * C_ * C_ + C_ * C_)]; // qkv_w bf16 ; out_w bf16
__device__ bf16 g_qk[(size_t)B_ * NPIX * 2 * C_];    // (b,p,o) o in [0,1024)
__device__ bf16 g_vt[(size_t)B_ * C_ * NPIX];        // (b,c,p)
__device__ bf16 g_p [(size_t)B_ * NPIX * NPIX];      // scores / probs (b,i,j)
__device__ bf16 g_ao[(size_t)B_ * NPIX * C_];        // (b,i,c)

// ------------------------------- helpers -----------------------------------
__device__ __forceinline__ uint32_t smem_u32(const void* p) {
    return (uint32_t)__cvta_generic_to_shared(p);
}
__device__ __forceinline__ void cp16(uint32_t dst, const void* src) {
    asm volatile("cp.async.cg.shared.global [%0], [%1], 16;\n" :: "r"(dst), "l"(src));
}
__device__ __forceinline__ void cp_commit() { asm volatile("cp.async.commit_group;\n"); }
template <int N> __device__ __forceinline__ void cp_wait() {
    asm volatile("cp.async.wait_group %0;\n" :: "n"(N));
}
__device__ __forceinline__ void ldsm4(uint32_t& r0, uint32_t& r1, uint32_t& r2, uint32_t& r3,
                                      uint32_t addr) {
    asm volatile("ldmatrix.sync.aligned.m8n8.x4.shared.b16 {%0,%1,%2,%3}, [%4];\n"
                 : "=r"(r0), "=r"(r1), "=r"(r2), "=r"(r3) : "r"(addr));
}
__device__ __forceinline__ void mma16816(float c[4],
                                         uint32_t a0, uint32_t a1, uint32_t a2, uint32_t a3,
                                         uint32_t b0, uint32_t b1) {
    asm volatile(
        "mma.sync.aligned.m16n8k16.row.col.f32.bf16.bf16.f32 "
        "{%0,%1,%2,%3},{%4,%5,%6,%7},{%8,%9},{%0,%1,%2,%3};\n"
        : "+f"(c[0]), "+f"(c[1]), "+f"(c[2]), "+f"(c[3])
        : "r"(a0), "r"(a1), "r"(a2), "r"(a3), "r"(b0), "r"(b1));
}

// --------------------------- fp32 -> bf16 convert ---------------------------
__global__ void f2bf_kernel(const float4* __restrict__ a, __nv_bfloat162* __restrict__ o, int n4)
{
    int i = blockIdx.x * 256 + threadIdx.x;
    if (i < n4) {
        float4 v = a[i];
        o[2 * i + 0] = __floats2bfloat162_rn(v.x, v.y);
        o[2 * i + 1] = __floats2bfloat162_rn(v.z, v.w);
    }
}

// --------------- GroupNorm + transpose: x(b,c,p) -> hb(b,p,c) bf16 ----------
__global__ void gn_t_kernel(const float* __restrict__ x,
                            const float* __restrict__ gw,
                            const float* __restrict__ gb,
                            bf16* __restrict__ hb)
{
    const int grp = blockIdx.x;          // b*32 + g
    const int b   = grp >> 5;
    const int g   = grp & 31;
    const float* xg = x + (size_t)grp * (CPG * NPIX);
    const int tid = threadIdx.x;

    // ---- stats ----
    float s = 0.f, ss = 0.f;
    const float4* x4 = (const float4*)xg;
    #pragma unroll 4
    for (int i = tid; i < (CPG * NPIX) / 4; i += 256) {
        float4 v = x4[i];
        s  += v.x + v.y + v.z + v.w;
        ss += v.x * v.x + v.y * v.y + v.z * v.z + v.w * v.w;
    }
    __shared__ float sh[64];
    #pragma unroll
    for (int o = 16; o; o >>= 1) {
        s  += __shfl_xor_sync(~0u, s, o);
        ss += __shfl_xor_sync(~0u, ss, o);
    }
    if ((tid & 31) == 0) { sh[tid >> 5] = s; sh[(tid >> 5) + 32] = ss; }
    __syncthreads();
    __shared__ float s_mu, s_rs;
    if (tid < 32) {
        float a = (tid < 8) ? sh[tid]      : 0.f;
        float c = (tid < 8) ? sh[tid + 32] : 0.f;
        #pragma unroll
        for (int o = 4; o; o >>= 1) {
            a += __shfl_xor_sync(~0u, a, o);
            c += __shfl_xor_sync(~0u, c, o);
        }
        if (tid == 0) {
            float mu  = a / (float)(CPG * NPIX);
            float var = c / (float)(CPG * NPIX) - mu * mu;
            s_mu = mu;
            s_rs = rsqrtf(var + 1e-5f);
        }
    }
    __syncthreads();

    __shared__ float s_sc[CPG], s_sb[CPG];
    if (tid < CPG) {
        float w = gw[g * CPG + tid] * s_rs;
        s_sc[tid] = w;
        s_sb[tid] = gb[g * CPG + tid] - s_mu * w;
    }
    __syncthreads();

    // ---- normalize + transpose write: 32B per pixel ----
    for (int p = tid; p < NPIX; p += 256) {
        __nv_bfloat162 pk[8];
        #pragma unroll
        for (int c2 = 0; c2 < 8; c2++) {
            float v0 = xg[(2 * c2 + 0) * NPIX + p] * s_sc[2 * c2 + 0] + s_sb[2 * c2 + 0];
            float v1 = xg[(2 * c2 + 1) * NPIX + p] * s_sc[2 * c2 + 1] + s_sb[2 * c2 + 1];
            pk[c2] = __floats2bfloat162_rn(v0, v1);
        }
        uint4* dst = (uint4*)(hb + ((size_t)(b * NPIX + p)) * C_ + g * CPG);
        dst[0] = *(uint4*)&pk[0];
        dst[1] = *(uint4*)&pk[4];
    }
}

// ----------------------- TN bf16 GEMM, mma.sync -----------------------------
// C[m,n] = alpha * sum_k A[m,k]*B[n,k]  (+biasM[m]) (+biasN[n]) (+resid) -> fp32 or bf16
#define BM 128
#define BN 128
#define BK 64
#define STAGES 3
#define GTHREADS 256
#define GSMEM (STAGES * (BM + BN) * BK * 2)

#define LOAD_STAGE(s_, kt_) do {                                                   \
    bf16* as_ = As + (s_) * (BM * BK);                                             \
    bf16* bs_ = Bs + (s_) * (BN * BK);                                             \
    const bf16* ga_ = A  + (long long)(kt_) * BK + lchunk * 8;                     \
    const bf16* gb_ = Bm + (long long)(kt_) * BK + lchunk * 8;                     \
    _Pragma("unroll")                                                              \
    for (int p_ = 0; p_ < 4; p_++) {                                               \
        int r_ = lrow + p_ * 32;                                                   \
        int sw_ = (lchunk ^ (r_ & 7)) << 3;                                        \
        cp16(smem_u32(as_ + r_ * BK + sw_), ga_ + (long long)(m0 + r_) * lda);     \
        cp16(smem_u32(bs_ + r_ * BK + sw_), gb_ + (long long)(n0 + r_) * ldb);     \
    }                                                                              \
} while (0)

__global__ void __launch_bounds__(GTHREADS)
bgemm_tn(const bf16* __restrict__ A, const bf16* __restrict__ Bm,
         float* __restrict__ Cf, bf16* __restrict__ Cb,
         int M, int N, int K, int lda, int ldb, int ldc,
         long long bA, long long bB, long long bC,
         float alpha,
         const float* __restrict__ biasM, const float* __restrict__ biasN,
         const float* __restrict__ resid)
{
    extern __shared__ bf16 smem[];
    bf16* As = smem;
    bf16* Bs = smem + STAGES * BM * BK;

    const int bz = blockIdx.z;
    A  += (long long)bz * bA;
    Bm += (long long)bz * bB;
    if (Cf)    Cf    += (long long)bz * bC;
    if (Cb)    Cb    += (long long)bz * bC;
    if (resid) resid += (long long)bz * bC;

    const int m0   = blockIdx.y * BM;
    const int n0   = blockIdx.x * BN;
    const int tid  = threadIdx.x;
    const int lane = tid & 31;
    const int wid  = tid >> 5;
    const int wm   = (wid & 1) * 64;     // warp m-offset inside tile
    const int wn   = (wid >> 1) * 32;    // warp n-offset inside tile
    const int lrow   = tid >> 3;         // loader row 0..31
    const int lchunk = tid & 7;          // loader 16B chunk 0..7

    const int nk = K / BK;

    #pragma unroll
    for (int s = 0; s < STAGES - 1; s++) { LOAD_STAGE(s, s); cp_commit(); }

    float acc[4][4][4] = {};

    for (int kt = 0; kt < nk; kt++) {
        cp_wait<STAGES - 2>();
        __syncthreads();
        if (kt + STAGES - 1 < nk) LOAD_STAGE((kt + STAGES - 1) % STAGES, kt + STAGES - 1);
        cp_commit();

        bf16* as = As + (kt % STAGES) * (BM * BK);
        bf16* bs = Bs + (kt % STAGES) * (BN * BK);

        #pragma unroll
        for (int ks = 0; ks < 4; ks++) {           // 4 x k16 inside BK=64
            uint32_t af[4][4], bfv[2][4];
            const int kc = ks * 2 + (lane >> 4);   // 16B chunk index
            #pragma unroll
            for (int mi = 0; mi < 4; mi++) {
                int r = wm + mi * 16 + (lane & 15);
                ldsm4(af[mi][0], af[mi][1], af[mi][2], af[mi][3],
                      smem_u32(as + r * BK + ((kc ^ (r & 7)) << 3)));
            }
            #pragma unroll
            for (int nj = 0; nj < 2; nj++) {
                int r = wn + nj * 16 + (lane & 15);
                ldsm4(bfv[nj][0], bfv[nj][1], bfv[nj][2], bfv[nj][3],
                      smem_u32(bs + r * BK + ((kc ^ (r & 7)) << 3)));
            }
            #pragma unroll
            for (int mi = 0; mi < 4; mi++)
                #pragma unroll
                for (int nj = 0; nj < 4; nj++) {
                    int hi = nj >> 1, lo = nj & 1;
                    mma16816(acc[mi][nj],
                             af[mi][0], af[mi][1], af[mi][2], af[mi][3],
                             bfv[hi][lo], bfv[hi][lo + 2]);
                }
        }
        __syncthreads();
    }

    // ---- epilogue ----
    const int tq = lane >> 2, tr = lane & 3;
    #pragma unroll
    for (int mi = 0; mi < 4; mi++) {
        #pragma unroll
        for (int h = 0; h < 2; h++) {
            int m = m0 + wm + mi * 16 + tq + h * 8;
            float bm = biasM ? biasM[m] : 0.f;
            #pragma unroll
            for (int nj = 0; nj < 4; nj++) {
                int n = n0 + wn + nj * 8 + tr * 2;
                float v0 = acc[mi][nj][2 * h + 0] * alpha + bm;
                float v1 = acc[mi][nj][2 * h + 1] * alpha + bm;
                if (biasN) { v0 += biasN[n]; v1 += biasN[n + 1]; }
                long long ci = (long long)m * ldc + n;
                if (Cf) {
                    if (resid) { v0 += resid[ci]; v1 += resid[ci + 1]; }
                    *(float2*)(Cf + ci) = make_float2(v0, v1);
                } else {
                    *(__nv_bfloat162*)(Cb + ci) = __floats2bfloat162_rn(v0, v1);
                }
            }
        }
    }
}

// --------------------------- bf16 row softmax -------------------------------
__global__ void softmax_bf_kernel(bf16* __restrict__ S)
{
    __nv_bfloat162* rp = (__nv_bfloat162*)(S + (long long)blockIdx.x * NPIX);
    const int tid = threadIdx.x;

    float2 v[8];
    float mx = -1e30f;
    #pragma unroll
    for (int i = 0; i < 8; i++) {
        v[i] = __bfloat1622float2(rp[tid + i * 256]);
        mx = fmaxf(mx, fmaxf(v[i].x, v[i].y));
    }
    __shared__ float sh[8];
    #pragma unroll
    for (int o = 16; o; o >>= 1) mx = fmaxf(mx, __shfl_xor_sync(~0u, mx, o));
    if ((tid & 31) == 0) sh[tid >> 5] = mx;
    __syncthreads();
    if (tid < 32) {
        float m2 = (tid < 8) ? sh[tid] : -1e30f;
        #pragma unroll
        for (int o = 4; o; o >>= 1) m2 = fmaxf(m2, __shfl_xor_sync(~0u, m2, o));
        if (tid == 0) sh[0] = m2;
    }
    __syncthreads();
    mx = sh[0];
    __syncthreads();

    float s = 0.f;
    #pragma unroll
    for (int i = 0; i < 8; i++) {
        v[i].x = __expf(v[i].x - mx);
        v[i].y = __expf(v[i].y - mx);
        s += v[i].x + v[i].y;
    }
    #pragma unroll
    for (int o = 16; o; o >>= 1) s += __shfl_xor_sync(~0u, s, o);
    if ((tid & 31) == 0) sh[tid >> 5] = s;
    __syncthreads();
    if (tid < 32) {
        float s2 = (tid < 8) ? sh[tid] : 0.f;
        #pragma unroll
        for (int o = 4; o; o >>= 1) s2 += __shfl_xor_sync(~0u, s2, o);
        if (tid == 0) sh[0] = s2;
    }
    __syncthreads();
    const float inv = 1.f / sh[0];
    #pragma unroll
    for (int i = 0; i < 8; i++)
        rp[tid + i * 256] = __floats2bfloat162_rn(v[i].x * inv, v[i].y * inv);
}

// ---------------------------------------------------------------------------
extern "C" void kernel_launch(void* const* d_in, const int* in_sizes, int n_in,
                              void* d_out, int out_size)
{
    const float* x     = (const float*)d_in[0];
    const float* gn_w  = (const float*)d_in[1];
    const float* gn_b  = (const float*)d_in[2];
    const float* qkv_w = (const float*)d_in[3];
    const float* qkv_b = (const float*)d_in[4];
    const float* out_w = (const float*)d_in[5];
    const float* out_b = (const float*)d_in[6];
    float* out = (float*)d_out;

    void *p0, *p1, *p2, *p3, *p4, *p5;
    cudaGetSymbolAddress(&p0, g_hb);
    cudaGetSymbolAddress(&p1, g_w);
    cudaGetSymbolAddress(&p2, g_qk);
    cudaGetSymbolAddress(&p3, g_vt);
    cudaGetSymbolAddress(&p4, g_p);
    cudaGetSymbolAddress(&p5, g_ao);
    bf16* hb = (bf16*)p0;
    bf16* w  = (bf16*)p1;
    bf16* qk = (bf16*)p2;
    bf16* vt = (bf16*)p3;
    bf16* pb = (bf16*)p4;
    bf16* ao = (bf16*)p5;

    cudaFuncSetAttribute(bgemm_tn, cudaFuncAttributeMaxDynamicSharedMemorySize, GSMEM);

    // 0) weights -> bf16
    {
        int n4 = (3 * C_ * C_) / 4;
        f2bf_kernel<<<(n4 + 255) / 256, 256>>>((const float4*)qkv_w, (__nv_bfloat162*)w, n4);
        int m4 = (C_ * C_) / 4;
        f2bf_kernel<<<(m4 + 255) / 256, 256>>>((const float4*)out_w,
                                               (__nv_bfloat162*)(w + 3 * C_ * C_), m4);
    }

    // 1) GroupNorm + transpose -> hb(b,p,c)
    gn_t_kernel<<<B_ * GROUPS, 256>>>(x, gn_w, gn_b, hb);

    // 2) q,k: qk[b,p,o] = sum_c hb[b,p,c] * Wqk[o,c] + qkv_b[o]   (o in [0,1024))
    {
        dim3 grid((2 * C_) / BN, NPIX / BM, B_);
        bgemm_tn<<<grid, GTHREADS, GSMEM>>>(hb, w, nullptr, qk,
            NPIX, 2 * C_, C_, C_, C_, 2 * C_,
            (long long)NPIX * C_, 0LL, (long long)NPIX * 2 * C_,
            1.0f, nullptr, qkv_b, nullptr);
    }

    // 2b) v: vt[b,c,p] = sum_c' Wv[c,c'] * hb[b,p,c'] + qkv_b[1024+c]
    {
        dim3 grid(NPIX / BN, C_ / BM, B_);
        bgemm_tn<<<grid, GTHREADS, GSMEM>>>(w + (size_t)2 * C_ * C_, hb, nullptr, vt,
            C_, NPIX, C_, C_, C_, NPIX,
            0LL, (long long)NPIX * C_, (long long)C_ * NPIX,
            1.0f, qkv_b + 2 * C_, nullptr, nullptr);
    }

    // 3) scores: P[b,i,j] = scale * sum_c qk[b,i,c] * qk[b,j,512+c]
    {
        dim3 grid(NPIX / BN, NPIX / BM, B_);
        const float scale = 1.0f / sqrtf((float)C_);
        bgemm_tn<<<grid, GTHREADS, GSMEM>>>(qk, qk + C_, nullptr, pb,
            NPIX, NPIX, C_, 2 * C_, 2 * C_, NPIX,
            (long long)NPIX * 2 * C_, (long long)NPIX * 2 * C_, (long long)NPIX * NPIX,
            scale, nullptr, nullptr, nullptr);
    }

    // 4) softmax rows (bf16 in-place)
    softmax_bf_kernel<<<B_ * NPIX, 256>>>(pb);

    // 5) ao[b,i,c] = sum_j P[b,i,j] * vt[b,c,j]
    {
        dim3 grid(C_ / BN, NPIX / BM, B_);
        bgemm_tn<<<grid, GTHREADS, GSMEM>>>(pb, vt, nullptr, ao,
            NPIX, C_, NPIX, NPIX, NPIX, C_,
            (long long)NPIX * NPIX, (long long)C_ * NPIX, (long long)NPIX * C_,
            1.0f, nullptr, nullptr, nullptr);
    }

    // 6) out[b,o,p] = sum_c Wo[o,c] * ao[b,p,c] + out_b[o] + x[b,o,p]
    {
        dim3 grid(NPIX / BN, C_ / BM, B_);
        bgemm_tn<<<grid, GTHREADS, GSMEM>>>(w + (size_t)3 * C_ * C_, ao, out, nullptr,
            C_, NPIX, C_, C_, C_, NPIX,
            0LL, (long long)NPIX * C_, (long long)C_ * NPIX,
            1.0f, out_b, nullptr, x);
    }
}